// round 4
// baseline (speedup 1.0000x reference)
#include <cuda_runtime.h>
#include <math.h>

#define THRE_TIMES 5.0f
#define THRE_POINT 1000.0f
#define RPT 4   // output rows per thread

// ---------------------------------------------------------------------------
// Fast kernel: warp = 128 contiguous columns (32 lanes x float4), halos via
// shuffle, all (RPT+2) row loads front-batched, horizontal 3-sums hoisted
// (computed once per source row, reused by 3 output rows).
// Requires W % 128 == 0, H % (8*RPT) == 0.
// ---------------------------------------------------------------------------
__global__ __launch_bounds__(256, 4) void dpr_shfl_kernel(
    const float* __restrict__ img, float* __restrict__ out, int H, int W)
{
    const int lane = threadIdx.x;                       // 0..31
    const int c4   = (blockIdx.x * 32 + lane) * 4;      // first of 4 columns
    const int r0   = (blockIdx.y * blockDim.y + threadIdx.y) * RPT;

    float4 arr[RPT + 2];
    float  lft[RPT + 2], rgt[RPT + 2];
    float  hs[RPT + 2][4];

    // Front-batched vector loads (rows r0-1 .. r0+RPT)
#pragma unroll
    for (int s = 0; s < RPT + 2; ++s) {
        int rr = r0 - 1 + s;
        if (rr >= 0 && rr < H)
            arr[s] = *reinterpret_cast<const float4*>(img + (size_t)rr * W + c4);
        else
            arr[s] = make_float4(0.f, 0.f, 0.f, 0.f);
    }

    // Halos via shuffle; lanes 0/31 patch from global (2 LDG/warp/row)
#pragma unroll
    for (int s = 0; s < RPT + 2; ++s) {
        int rr = r0 - 1 + s;
        bool valid = (rr >= 0) && (rr < H);
        float lw = __shfl_up_sync(0xffffffffu, arr[s].w, 1);
        float rw = __shfl_down_sync(0xffffffffu, arr[s].x, 1);
        if (lane == 0)
            lw = (valid && c4 > 0) ? __ldg(img + (size_t)rr * W + c4 - 1) : 0.0f;
        if (lane == 31)
            rw = (valid && c4 + 4 < W) ? __ldg(img + (size_t)rr * W + c4 + 4) : 0.0f;
        lft[s] = lw; rgt[s] = rw;
    }

    // Hoisted horizontal 3-sums (same association as before: (a+b)+c)
#pragma unroll
    for (int s = 0; s < RPT + 2; ++s) {
        hs[s][0] = lft[s]  + arr[s].x + arr[s].y;
        hs[s][1] = arr[s].x + arr[s].y + arr[s].z;
        hs[s][2] = arr[s].y + arr[s].z + arr[s].w;
        hs[s][3] = arr[s].z + arr[s].w + rgt[s];
    }

    const bool colEdge = (c4 == 0) | (c4 + 4 >= W);
    const bool rowEdge = (r0 == 0) | (r0 + RPT >= H);
    const bool edge = colEdge | rowEdge;

#pragma unroll
    for (int ri = 0; ri < RPT; ++ri) {
        const int r = r0 + ri;
        const float4 up  = arr[ri];
        const float4 mid = arr[ri + 1];
        const float4 dn  = arr[ri + 2];
        const float lm = lft[ri + 1], rm = rgt[ri + 1];

        float v[4]  = { mid.x, mid.y, mid.z, mid.w };
        float ns[4];
        ns[0] = up.x + dn.x + lm + mid.y;
        ns[1] = up.y + dn.y + mid.x + mid.z;
        ns[2] = up.z + dn.z + mid.y + mid.w;
        ns[3] = up.w + dn.w + mid.z + rm;

        float o[4];
        if (!edge) {
#pragma unroll
            for (int j = 0; j < 4; ++j) {
                float sum9 = hs[ri][j] + hs[ri + 1][j] + hs[ri + 2][j];
                float mean = sum9 * (1.0f / 9.0f);
                float thr  = fminf(THRE_TIMES * mean, THRE_POINT);
                float rep  = floorf(ns[j] * 0.25f);
                o[j] = (v[j] > thr) ? rep : v[j];
            }
        } else {
            const bool rtop = (r == 0);
            const bool rbot = (r == H - 1);
            const float cnt_row = (float)((r > 0) + (r < H - 1));
#pragma unroll
            for (int j = 0; j < 4; ++j) {
                int c = c4 + j;
                float sum9 = hs[ri][j] + hs[ri + 1][j] + hs[ri + 2][j];
                float mean = sum9 * (1.0f / 9.0f);
                bool cl = (c == 0), cr = (c == W - 1);
                float coeff = 1.0f;
                if (rtop || rbot || cl || cr)
                    coeff = ((rtop || rbot) && (cl || cr)) ? 2.25f : 1.5f;
                float thr = fminf(THRE_TIMES * mean * coeff, THRE_POINT);
                float cnt = cnt_row + (float)((c > 0) + (c < W - 1));
                float rep = floorf(ns[j] / cnt);
                o[j] = (v[j] > thr) ? rep : v[j];
            }
        }

        __stcs(reinterpret_cast<float4*>(out + (size_t)r * W + c4),
               make_float4(o[0], o[1], o[2], o[3]));
    }
}

// ---------------------------------------------------------------------------
// Generic fallback for shapes not matching the warp tile.
// ---------------------------------------------------------------------------
__global__ __launch_bounds__(256) void dpr_generic_kernel(
    const float* __restrict__ img, float* __restrict__ out, int H, int W)
{
    const int Wq = (W + 3) >> 2;
    const int qx = blockIdx.x * blockDim.x + threadIdx.x;
    if (qx >= Wq) return;
    const int c4 = qx << 2;
    const int r = blockIdx.y * blockDim.y + threadIdx.y;
    if (r >= H) return;

    float rowv[3][6];
#pragma unroll
    for (int k = 0; k < 3; ++k) {
        int rr = r + k - 1;
        if (rr < 0 || rr >= H) {
#pragma unroll
            for (int j = 0; j < 6; ++j) rowv[k][j] = 0.0f;
        } else {
            const float* p = img + (size_t)rr * W + c4;
#pragma unroll
            for (int j = 0; j < 4; ++j)
                rowv[k][j + 1] = (c4 + j < W) ? p[j] : 0.0f;
            rowv[k][0] = (c4 > 0) ? p[-1] : 0.0f;
            rowv[k][5] = (c4 + 4 < W) ? p[4] : 0.0f;
        }
    }
    const bool rtop = (r == 0), rbot = (r == H - 1);
    const float cnt_row = (float)((r > 0) + (r < H - 1));
#pragma unroll
    for (int j = 0; j < 4; ++j) {
        int c = c4 + j;
        if (c >= W) break;
        float v = rowv[1][j + 1];
        float sum9 = rowv[0][j] + rowv[0][j + 1] + rowv[0][j + 2]
                   + rowv[1][j] + rowv[1][j + 1] + rowv[1][j + 2]
                   + rowv[2][j] + rowv[2][j + 1] + rowv[2][j + 2];
        float mean = sum9 * (1.0f / 9.0f);
        bool cl = (c == 0), cr = (c == W - 1);
        float coeff = 1.0f;
        if (rtop || rbot || cl || cr)
            coeff = ((rtop || rbot) && (cl || cr)) ? 2.25f : 1.5f;
        bool mask = (v > THRE_TIMES * mean * coeff) || (v > THRE_POINT);
        float nsum = rowv[0][j + 1] + rowv[2][j + 1] + rowv[1][j] + rowv[1][j + 2];
        float cnt = cnt_row + (float)((c > 0) + (c < W - 1));
        out[(size_t)r * W + c] = mask ? floorf(nsum / cnt) : v;
    }
}

extern "C" void kernel_launch(void* const* d_in, const int* in_sizes, int n_in,
                              void* d_out, int out_size)
{
    const float* img = (const float*)d_in[0];
    float* out = (float*)d_out;

    int n = in_sizes[0];
    int W = (int)(sqrt((double)n) + 0.5);
    int H = n / W;

    if (W % 128 == 0 && H % (8 * RPT) == 0) {
        dim3 block(32, 8);
        dim3 grid(W / 128, H / (8 * RPT));
        dpr_shfl_kernel<<<grid, block>>>(img, out, H, W);
    } else {
        dim3 block(64, 4);
        dim3 grid(((W + 3) / 4 + block.x - 1) / block.x,
                  (H + block.y - 1) / block.y);
        dpr_generic_kernel<<<grid, block>>>(img, out, H, W);
    }
}